// round 2
// baseline (speedup 1.0000x reference)
#include <cuda_runtime.h>

// Problem constants (fixed shapes from reference setup_inputs)
#define BATCH   4
#define NCH     4      // segmentation channels (class 0 = background)
#define NCLS    3      // foreground classes 1..3
#define NPTS    8192   // W*H = 64*128
#define CHUNK   256
#define MAXK    8192   // worst-case kept list per (b, class)
#define RADIUS2 9.0f

// Dynamic shared layout:
//   float2 kept[MAXK]                      65536 B
//   float  cx[CHUNK], cy[CHUNK]             2048 B
//   int    cidx[CHUNK]                      1024 B
//   unsigned conflict[CHUNK][8]             8192 B
static const int SMEM_BYTES = MAXK * 8 + CHUNK * 4 * 2 + CHUNK * 4 + CHUNK * 8 * 4;

__global__ __launch_bounds__(CHUNK, 1)
void radius_nms_kernel(const float* __restrict__ seg,
                       const float* __restrict__ lidar,
                       float* __restrict__ out) {
    extern __shared__ char smem_raw[];
    float2*   kept     = (float2*)smem_raw;
    float*    cx       = (float*)(kept + MAXK);
    float*    cy       = cx + CHUNK;
    int*      cidx     = (int*)(cy + CHUNK);
    unsigned* conflict = (unsigned*)(cidx + CHUNK);

    __shared__ unsigned keepbits[8];
    __shared__ int warpsum[8];
    __shared__ unsigned char pointkeep[CHUNK];
    __shared__ int sM;

    const int blk  = blockIdx.x;          // 0..11
    const int b    = blk / NCLS;
    const int cls  = (blk % NCLS) + 1;    // foreground class 1..3
    const int t    = threadIdx.x;
    const int warp = t >> 5;
    const int lane = t & 31;

    const float* segb = seg + (size_t)b * NCH * NPTS;
    const float* lx   = lidar + (size_t)b * 5 * NPTS;          // lidar channel 0 = x
    const float* ly   = lx + NPTS;                              // channel 1 = y

    float* coord_out = out + (size_t)(b * NCLS + (cls - 1)) * NPTS * 2;
    float* keep_out  = out + (size_t)BATCH * NCLS * NPTS * 2
                           + (size_t)(b * NCLS + (cls - 1)) * NPTS;

    if (t == 0) sM = 0;
    __syncthreads();

    for (int base = 0; base < NPTS; base += CHUNK) {
        const int n = base + t;

        // ---- per-pixel argmax class (first-max tie-break, same as jnp.argmax)
        float s0 = segb[0 * NPTS + n];
        float s1 = segb[1 * NPTS + n];
        float s2 = segb[2 * NPTS + n];
        float s3 = segb[3 * NPTS + n];
        int   am = 0; float mv = s0;
        if (s1 > mv) { mv = s1; am = 1; }
        if (s2 > mv) { mv = s2; am = 2; }
        if (s3 > mv) { mv = s3; am = 3; }
        const bool valid = (am == cls);

        const float x = lx[n];
        const float y = ly[n];

        pointkeep[t] = 0;
        const int M = sM;

        // ---- check against committed kept list (parallel over chunk points)
        bool alive = valid;
        if (alive) {
            for (int j = 0; j < M; j++) {
                float2 k = kept[j];
                float dx = x - k.x, dy = y - k.y;
                if (dx * dx + dy * dy <= RADIUS2) { alive = false; break; }
            }
        }

        // ---- block exclusive scan of 'alive' -> compact candidates in order
        unsigned bal = __ballot_sync(0xffffffffu, alive);
        if (lane == 0) warpsum[warp] = __popc(bal);
        __syncthreads();
        int woff = 0;
        #pragma unroll
        for (int w = 0; w < 8; w++) if (w < warp) woff += warpsum[w];
        int A = 0;
        #pragma unroll
        for (int w = 0; w < 8; w++) A += warpsum[w];
        const int pos = woff + __popc(bal & ((1u << lane) - 1u));
        if (alive) { cx[pos] = x; cy[pos] = y; cidx[pos] = t; }
        __syncthreads();

        // ---- intra-chunk pairwise conflict bitmatrix (candidate t vs j < t)
        if (t < A) {
            unsigned row[8] = {0, 0, 0, 0, 0, 0, 0, 0};
            const float xi = cx[t], yi = cy[t];
            for (int j = 0; j < t; j++) {
                float dx = xi - cx[j], dy = yi - cy[j];
                if (dx * dx + dy * dy <= RADIUS2) row[j >> 5] |= (1u << (j & 31));
            }
            #pragma unroll
            for (int w = 0; w < 8; w++) conflict[t * 8 + w] = row[w];
        }
        __syncthreads();

        // ---- serial greedy over candidates (single thread, pure bit-ops)
        // conflict row i is lower-triangular (bits j < i). Candidate i is kept
        // iff no EARLIER KEPT candidate conflicts with it: (row_i & kb) == 0.
        if (t == 0) {
            unsigned kb[8] = {0, 0, 0, 0, 0, 0, 0, 0};
            for (int i = 0; i < A; i++) {
                const unsigned* r = &conflict[i * 8];
                unsigned hit = 0;
                #pragma unroll
                for (int w = 0; w < 8; w++) hit |= (r[w] & kb[w]);
                if (hit == 0) kb[i >> 5] |= (1u << (i & 31));
            }
            #pragma unroll
            for (int w = 0; w < 8; w++) keepbits[w] = kb[w];
        }
        __syncthreads();

        // ---- append kept candidates to the kept list (order-preserving scan)
        bool keepme = false;
        if (t < A) keepme = (keepbits[t >> 5] >> (t & 31)) & 1u;
        unsigned kbal = __ballot_sync(0xffffffffu, keepme);
        if (lane == 0) warpsum[warp] = __popc(kbal);
        __syncthreads();
        int koff = M;
        #pragma unroll
        for (int w = 0; w < 8; w++) if (w < warp) koff += warpsum[w];
        int totk = 0;
        #pragma unroll
        for (int w = 0; w < 8; w++) totk += warpsum[w];
        const int kpos = koff + __popc(kbal & ((1u << lane) - 1u));
        if (keepme) {
            kept[kpos] = make_float2(cx[t], cy[t]);
            pointkeep[cidx[t]] = 1;
        }
        if (t == 0) sM = M + totk;
        __syncthreads();

        // ---- write outputs for every point in the chunk
        const float kf = pointkeep[t] ? 1.0f : 0.0f;
        keep_out[n] = kf;
        reinterpret_cast<float2*>(coord_out)[n] = make_float2(x * kf, y * kf);

        __syncthreads();   // protect pointkeep / kept / sM before next chunk
    }
}

extern "C" void kernel_launch(void* const* d_in, const int* in_sizes, int n_in,
                              void* d_out, int out_size) {
    (void)in_sizes; (void)n_in; (void)out_size;
    const float* seg   = (const float*)d_in[0];
    const float* lidar = (const float*)d_in[1];
    float* out = (float*)d_out;

    cudaFuncSetAttribute(radius_nms_kernel,
                         cudaFuncAttributeMaxDynamicSharedMemorySize, SMEM_BYTES);
    radius_nms_kernel<<<BATCH * NCLS, CHUNK, SMEM_BYTES>>>(seg, lidar, out);
}

// round 3
// speedup vs baseline: 4.7902x; 4.7902x over previous
#include <cuda_runtime.h>

// Problem constants (fixed shapes from reference setup_inputs)
#define BATCH   4
#define NCH     4      // segmentation channels (class 0 = background)
#define NCLS    3      // foreground classes 1..3
#define NPTS    8192   // W*H = 64*128
#define CHUNK   256
#define MAXK    8192   // worst-case kept list per (b, class)
#define RADIUS2 9.0f

// Spatial grid over kept points: 4m cells, 96x96 covering [-192, 192).
// Any pair with d <= 3m is within +-1 cell (cells 2 apart have gap >= 4m > 3m).
// Out-of-range coords clamp to border cells -> only adds false candidates,
// the exact d^2 test still decides (correctness preserved).
#define GC      96
#define GCELLS  (GC * GC)
#define GINV    0.25f
#define GORG    192.0f

// Dynamic shared layout (offsets in bytes):
//   float2   kept[MAXK]        @ 0        65536
//   int      nxt [MAXK]        @ 65536    32768
//   int      head[GCELLS]      @ 98304    36864
//   float    cx[CHUNK]         @ 135168    1024
//   float    cy[CHUNK]         @ 136192    1024
//   int      cidx[CHUNK]       @ 137216    1024
//   unsigned col[CHUNK*8]      @ 138240    8192   (32B-aligned rows)
static const int SMEM_BYTES = 146432;

__global__ __launch_bounds__(CHUNK, 1)
void radius_nms_kernel(const float* __restrict__ seg,
                       const float* __restrict__ lidar,
                       float* __restrict__ out) {
    extern __shared__ char smem_raw[];
    float2*   kept = (float2*)smem_raw;
    int*      nxt  = (int*)(smem_raw + 65536);
    int*      head = (int*)(smem_raw + 98304);
    float*    cx   = (float*)(smem_raw + 135168);
    float*    cy   = (float*)(smem_raw + 136192);
    int*      cidx = (int*)(smem_raw + 137216);
    unsigned* col  = (unsigned*)(smem_raw + 138240);

    __shared__ unsigned keepbits[8];
    __shared__ int warpsum[8];
    __shared__ unsigned char pointkeep[CHUNK];
    __shared__ int kcount;

    const int blk  = blockIdx.x;          // 0..11
    const int b    = blk / NCLS;
    const int cls  = (blk % NCLS) + 1;    // foreground class 1..3
    const int t    = threadIdx.x;
    const int warp = t >> 5;
    const int lane = t & 31;

    const float* segb = seg + (size_t)b * NCH * NPTS;
    const float* lx   = lidar + (size_t)b * 5 * NPTS;   // lidar ch 0 = x
    const float* ly   = lx + NPTS;                       // ch 1 = y

    float* coord_out = out + (size_t)(b * NCLS + (cls - 1)) * NPTS * 2;
    float* keep_out  = out + (size_t)BATCH * NCLS * NPTS * 2
                           + (size_t)(b * NCLS + (cls - 1)) * NPTS;

    // init grid heads + counter
    for (int i = t; i < GCELLS; i += CHUNK) head[i] = -1;
    if (t == 0) kcount = 0;
    __syncthreads();

    for (int base = 0; base < NPTS; base += CHUNK) {
        const int n = base + t;

        // ---- per-pixel argmax class (first-max tie-break, like jnp.argmax)
        float s0 = segb[0 * NPTS + n];
        float s1 = segb[1 * NPTS + n];
        float s2 = segb[2 * NPTS + n];
        float s3 = segb[3 * NPTS + n];
        int   am = 0; float mv = s0;
        if (s1 > mv) { mv = s1; am = 1; }
        if (s2 > mv) { mv = s2; am = 2; }
        if (s3 > mv) { mv = s3; am = 3; }
        const bool valid = (am == cls);

        const float x = lx[n];
        const float y = ly[n];

        pointkeep[t] = 0;

        // ---- check against committed kept points via the spatial grid
        bool alive = valid;
        if (alive) {
            int gx = (int)floorf((x + GORG) * GINV);
            int gy = (int)floorf((y + GORG) * GINV);
            gx = min(max(gx, 0), GC - 1);
            gy = min(max(gy, 0), GC - 1);
            #pragma unroll
            for (int dy = -1; dy <= 1 && alive; dy++) {
                int yy = gy + dy;
                if (yy < 0 || yy >= GC) continue;
                #pragma unroll
                for (int dx = -1; dx <= 1 && alive; dx++) {
                    int xx = gx + dx;
                    if (xx < 0 || xx >= GC) continue;
                    int h = head[yy * GC + xx];
                    while (h >= 0) {
                        float2 k = kept[h];
                        float ddx = x - k.x, ddy = y - k.y;
                        if (ddx * ddx + ddy * ddy <= RADIUS2) { alive = false; break; }
                        h = nxt[h];
                    }
                }
            }
        }

        // ---- block exclusive scan of 'alive' -> candidates in index order
        unsigned bal = __ballot_sync(0xffffffffu, alive);
        if (lane == 0) warpsum[warp] = __popc(bal);
        __syncthreads();                                     // S1
        int woff = 0;
        #pragma unroll
        for (int w = 0; w < 8; w++) if (w < warp) woff += warpsum[w];
        int A = 0;
        #pragma unroll
        for (int w = 0; w < 8; w++) A += warpsum[w];
        const int pos = woff + __popc(bal & ((1u << lane) - 1u));
        if (alive) { cx[pos] = x; cy[pos] = y; cidx[pos] = t; }
        __syncthreads();                                     // S2

        // ---- conflict COLUMNS via ballots: col[i] bit t set iff
        //      t > i and d2(cand_t, cand_i) <= r2.  (each warp owns its word)
        {
            const bool isc = (t < A);
            const float xt = isc ? cx[t] : 0.0f;
            const float yt = isc ? cy[t] : 0.0f;
            for (int i = 0; i < A; i++) {
                float dxx = xt - cx[i], dyy = yt - cy[i];
                bool c = isc && (t > i) && (dxx * dxx + dyy * dyy <= RADIUS2);
                unsigned m = __ballot_sync(0xffffffffu, c);
                if (lane == 0) col[i * 8 + warp] = m;
            }
        }
        __syncthreads();                                     // S3

        // ---- serial greedy over candidates (thread 0, bit-ops + LDS.128)
        if (t == 0) {
            unsigned supp[8] = {0,0,0,0,0,0,0,0};
            unsigned kb[8]   = {0,0,0,0,0,0,0,0};
            for (int i = 0; i < A; i++) {
                if (!((supp[i >> 5] >> (i & 31)) & 1u)) {
                    kb[i >> 5] |= (1u << (i & 31));
                    const uint4* c4 = (const uint4*)&col[i * 8];
                    uint4 a = c4[0], bb = c4[1];
                    supp[0] |= a.x;  supp[1] |= a.y;
                    supp[2] |= a.z;  supp[3] |= a.w;
                    supp[4] |= bb.x; supp[5] |= bb.y;
                    supp[6] |= bb.z; supp[7] |= bb.w;
                }
            }
            #pragma unroll
            for (int w = 0; w < 8; w++) keepbits[w] = kb[w];
        }
        __syncthreads();                                     // S4

        // ---- append kept candidates: kept[] + grid insert (order-free)
        bool keepme = false;
        if (t < A) keepme = (keepbits[t >> 5] >> (t & 31)) & 1u;
        if (keepme) {
            int kpos = atomicAdd(&kcount, 1);
            float kx = cx[t], ky = cy[t];
            kept[kpos] = make_float2(kx, ky);
            int gx = (int)floorf((kx + GORG) * GINV);
            int gy = (int)floorf((ky + GORG) * GINV);
            gx = min(max(gx, 0), GC - 1);
            gy = min(max(gy, 0), GC - 1);
            int cell = gy * GC + gx;
            int old = atomicExch(&head[cell], kpos);
            nxt[kpos] = old;
            pointkeep[cidx[t]] = 1;
        }
        __syncthreads();                                     // S5

        // ---- write outputs for every point in the chunk
        const float kf = pointkeep[t] ? 1.0f : 0.0f;
        keep_out[n] = kf;
        reinterpret_cast<float2*>(coord_out)[n] = make_float2(x * kf, y * kf);

        __syncthreads();                                     // S6 (protect pointkeep/grid)
    }
}

extern "C" void kernel_launch(void* const* d_in, const int* in_sizes, int n_in,
                              void* d_out, int out_size) {
    (void)in_sizes; (void)n_in; (void)out_size;
    const float* seg   = (const float*)d_in[0];
    const float* lidar = (const float*)d_in[1];
    float* out = (float*)d_out;

    cudaFuncSetAttribute(radius_nms_kernel,
                         cudaFuncAttributeMaxDynamicSharedMemorySize, SMEM_BYTES);
    radius_nms_kernel<<<BATCH * NCLS, CHUNK, SMEM_BYTES>>>(seg, lidar, out);
}

// round 4
// speedup vs baseline: 7.8582x; 1.6405x over previous
#include <cuda_runtime.h>

// Problem constants (fixed shapes from reference setup_inputs)
#define BATCH   4
#define NCH     4      // segmentation channels (class 0 = background)
#define NCLS    3      // foreground classes 1..3
#define NPTS    8192   // W*H = 64*128
#define CHUNK   256
#define MAXK    8192   // worst-case kept list per (b, class)
#define RADIUS2 9.0f

// Spatial grid over kept points: 4m cells, 96x96 covering [-192, 192).
// Any pair with d <= 3m is within +-1 cell. Out-of-range coords clamp to
// border cells -> only adds false candidates; exact d^2 test decides.
#define GC      96
#define GCELLS  (GC * GC)
#define GINV    0.25f
#define GORG    192.0f

// Dynamic shared layout (byte offsets):
//   float2   kept[MAXK]        @ 0        65536
//   int      nxt [MAXK]        @ 65536    32768
//   int      head[GCELLS]      @ 98304    36864
//   float    cx[CHUNK]         @ 135168    1024
//   float    cy[CHUNK]         @ 136192    1024
//   unsigned col[CHUNK*8]      @ 137216    8192   (32B-aligned columns)
static const int SMEM_BYTES = 145408;

__global__ __launch_bounds__(CHUNK, 1)
void radius_nms_kernel(const float* __restrict__ seg,
                       const float* __restrict__ lidar,
                       float* __restrict__ out) {
    extern __shared__ char smem_raw[];
    float2*   kept = (float2*)smem_raw;
    int*      nxt  = (int*)(smem_raw + 65536);
    int*      head = (int*)(smem_raw + 98304);
    float*    cx   = (float*)(smem_raw + 135168);
    float*    cy   = (float*)(smem_raw + 136192);
    unsigned* col  = (unsigned*)(smem_raw + 137216);

    __shared__ unsigned keepbits[8];
    __shared__ int warpsum[8];
    __shared__ int kcount;

    const int blk  = blockIdx.x;          // 0..11
    const int b    = blk / NCLS;
    const int cls  = (blk % NCLS) + 1;    // foreground class 1..3
    const int t    = threadIdx.x;
    const int warp = t >> 5;
    const int lane = t & 31;

    const float* segb = seg + (size_t)b * NCH * NPTS;
    const float* lx   = lidar + (size_t)b * 5 * NPTS;   // lidar ch 0 = x
    const float* ly   = lx + NPTS;                       // ch 1 = y

    float* coord_out = out + (size_t)(b * NCLS + (cls - 1)) * NPTS * 2;
    float* keep_out  = out + (size_t)BATCH * NCLS * NPTS * 2
                           + (size_t)(b * NCLS + (cls - 1)) * NPTS;

    for (int i = t; i < GCELLS; i += CHUNK) head[i] = -1;
    if (t == 0) kcount = 0;
    __syncthreads();

    for (int base = 0; base < NPTS; base += CHUNK) {
        const int n = base + t;

        // ---- per-pixel argmax class (first-max tie-break, like jnp.argmax)
        float s0 = segb[0 * NPTS + n];
        float s1 = segb[1 * NPTS + n];
        float s2 = segb[2 * NPTS + n];
        float s3 = segb[3 * NPTS + n];
        int   am = 0; float mv = s0;
        if (s1 > mv) { mv = s1; am = 1; }
        if (s2 > mv) { mv = s2; am = 2; }
        if (s3 > mv) { mv = s3; am = 3; }
        const bool valid = (am == cls);

        const float x = lx[n];
        const float y = ly[n];

        // ---- check against committed kept points via the spatial grid
        bool alive = valid;
        if (alive) {
            int gx = (int)floorf((x + GORG) * GINV);
            int gy = (int)floorf((y + GORG) * GINV);
            gx = min(max(gx, 0), GC - 1);
            gy = min(max(gy, 0), GC - 1);
            #pragma unroll
            for (int dy = -1; dy <= 1 && alive; dy++) {
                int yy = gy + dy;
                if (yy < 0 || yy >= GC) continue;
                #pragma unroll
                for (int dx = -1; dx <= 1 && alive; dx++) {
                    int xx = gx + dx;
                    if (xx < 0 || xx >= GC) continue;
                    int h = head[yy * GC + xx];
                    while (h >= 0) {
                        float2 k = kept[h];
                        float ddx = x - k.x, ddy = y - k.y;
                        if (ddx * ddx + ddy * ddy <= RADIUS2) { alive = false; break; }
                        h = nxt[h];
                    }
                }
            }
        }

        // ---- block exclusive scan of 'alive' -> candidates in index order
        unsigned bal = __ballot_sync(0xffffffffu, alive);
        if (lane == 0) warpsum[warp] = __popc(bal);
        __syncthreads();                                     // S1
        int woff = 0;
        #pragma unroll
        for (int w = 0; w < 8; w++) if (w < warp) woff += warpsum[w];
        int A = 0;
        #pragma unroll
        for (int w = 0; w < 8; w++) A += warpsum[w];
        const int pos = woff + __popc(bal & ((1u << lane) - 1u));
        if (alive) { cx[pos] = x; cy[pos] = y; }
        __syncthreads();                                     // S2

        // ---- conflict COLUMNS via ballots: col[i] bit t set iff
        //      t > i and d2(cand_t, cand_i) <= r2  (each warp owns its word)
        {
            const bool isc = (t < A);
            const float xt = isc ? cx[t] : 1.0e30f;
            const float yt = isc ? cy[t] : 1.0e30f;
            for (int i = 0; i < A; i++) {
                float dxx = xt - cx[i], dyy = yt - cy[i];
                bool c = (t > i) && (dxx * dxx + dyy * dyy <= RADIUS2);
                unsigned m = __ballot_sync(0xffffffffu, c);
                if (lane == 0) col[i * 8 + warp] = m;
            }
        }
        __syncthreads();                                     // S3

        // ---- serial greedy (thread 0). All bitset words stay in REGISTERS:
        //      outer loop over words is fully unrolled (constant indices).
        if (t == 0) {
            unsigned supp[8] = {0,0,0,0,0,0,0,0};
            unsigned kb[8]   = {0,0,0,0,0,0,0,0};
            #pragma unroll
            for (int w = 0; w < 8; w++) {
                const int lim = A - (w << 5);
                if (lim <= 0) break;
                const int nb = lim < 32 ? lim : 32;
                for (int k = 0; k < nb; k++) {
                    if (!((supp[w] >> k) & 1u)) {
                        kb[w] |= (1u << k);
                        const uint4* c4 = (const uint4*)&col[((w << 5) + k) * 8];
                        uint4 a = c4[0], bb = c4[1];
                        supp[0] |= a.x;  supp[1] |= a.y;
                        supp[2] |= a.z;  supp[3] |= a.w;
                        supp[4] |= bb.x; supp[5] |= bb.y;
                        supp[6] |= bb.z; supp[7] |= bb.w;
                    }
                }
            }
            #pragma unroll
            for (int w = 0; w < 8; w++) keepbits[w] = kb[w];
        }
        __syncthreads();                                     // S4

        // ---- resolve keep from own candidate slot, append, write outputs
        bool keepme = alive && ((keepbits[pos >> 5] >> (pos & 31)) & 1u);
        if (keepme) {
            int kpos = atomicAdd(&kcount, 1);
            kept[kpos] = make_float2(x, y);
            int gx = (int)floorf((x + GORG) * GINV);
            int gy = (int)floorf((y + GORG) * GINV);
            gx = min(max(gx, 0), GC - 1);
            gy = min(max(gy, 0), GC - 1);
            int cell = gy * GC + gx;
            int old = atomicExch(&head[cell], kpos);
            nxt[kpos] = old;
        }

        const float kf = keepme ? 1.0f : 0.0f;
        keep_out[n] = kf;
        reinterpret_cast<float2*>(coord_out)[n] = make_float2(x * kf, y * kf);

        __syncthreads();                                     // S5 (appends visible)
    }
}

extern "C" void kernel_launch(void* const* d_in, const int* in_sizes, int n_in,
                              void* d_out, int out_size) {
    (void)in_sizes; (void)n_in; (void)out_size;
    const float* seg   = (const float*)d_in[0];
    const float* lidar = (const float*)d_in[1];
    float* out = (float*)d_out;

    cudaFuncSetAttribute(radius_nms_kernel,
                         cudaFuncAttributeMaxDynamicSharedMemorySize, SMEM_BYTES);
    radius_nms_kernel<<<BATCH * NCLS, CHUNK, SMEM_BYTES>>>(seg, lidar, out);
}